// round 7
// baseline (speedup 1.0000x reference)
#include <cuda_runtime.h>

#define L 64
#define C 7
#define NSTEPS 126   // (L-1)*K, K=2, h=0.5
#define NG 7         // batches per group (CTA)
#define NCTA 586     // ceil(4096/7)

typedef unsigned long long ull;

__device__ __forceinline__ ull ffma2(ull a, ull b, ull c) {
    ull d;
    asm("fma.rn.f32x2 %0, %1, %2, %3;" : "=l"(d) : "l"(a), "l"(b), "l"(c));
    return d;
}
__device__ __forceinline__ ull pk2(float x, float y) {
    ull r;
    asm("mov.b64 %0, {%1, %2};" : "=l"(r) : "f"(x), "f"(y));
    return r;
}
__device__ __forceinline__ void upk2(ull v, float &x, float &y) {
    asm("mov.b64 {%0, %1}, %2;" : "=f"(x), "=f"(y) : "l"(v));
}
__device__ __forceinline__ float sp_(float x) {
    return fmaxf(x, 0.f) + __logf(1.f + __expf(-fabsf(x)));
}
__device__ __forceinline__ float tanh_(float x) {
    float y;
    asm("tanh.approx.f32 %0, %1;" : "=f"(y) : "f"(x));
    return y;
}

// cubic Hermite derivative: dX = m0 + (diff-m0)*f*(4-3f)
__device__ __forceinline__ float spline_eval(const float* __restrict__ xrow, float t) {
    int idx = (int)t;
    idx = min(idx, L - 2);
    float f = t - (float)idx;
    const float* p = xrow + idx * C;
    float x0 = __ldg(p);
    float x1 = __ldg(p + C);
    float diff = x1 - x0;
    float m0 = diff;
    if (idx > 0) m0 = x0 - __ldg(p - C);
    return fmaf((diff - m0) * f, fmaf(-3.f, f, 4.f), m0);
}

__global__ __launch_bounds__(128, 4)
void cde_kernel(const float* __restrict__ X,      // (4096,64,7)
                const float* __restrict__ Winit,  // (32,7)
                const float* __restrict__ binit,  // (32)
                const float* __restrict__ Wf1,    // (32,32)
                const float* __restrict__ bf1,    // (32)
                const float* __restrict__ Wf2,    // (224,32)
                const float* __restrict__ bf2,    // (224)
                const float* __restrict__ Wo1,    // (16,32)
                const float* __restrict__ bo1,    // (16)
                const float* __restrict__ Wo2,    // (3,16)
                const float* __restrict__ bo2,    // (3)
                float* __restrict__ out)          // (4096,3)
{
    // One CTA = 4 warps = one group serving 7 batches (slot 7 = dummy)
    __shared__ __align__(16) float sZ[8][32];        // zs per batch slot
    __shared__ __align__(16) float sH1[8][32];       // h1
    __shared__ __align__(16) float sM1[4][8][32];    // mm1 j-slice partials
    __shared__ __align__(16) float sPart[4][8][32];  // einsum c-slice partials
    __shared__ __align__(16) float sDX[3][8][8];     // spline values

    const int tid  = threadIdx.x;
    const int w    = tid >> 5;
    const int lane = tid & 31;               // = h
    const int cw   = (w + blockIdx.x) & 3;   // rotated role (SMSP load balance)
    const bool two_ch = (cw < 3);
    const int cg0  = two_ch ? 2 * cw : 6;    // first owned channel
    const int gbase = blockIdx.x * NG;

    // ---- Wf2 owned channels (j-pair packed) in registers ----
    ull wreg0[16], wreg1[16];
    float b20, b21;
    {
        const float2* wp = reinterpret_cast<const float2*>(Wf2 + (lane * C + cg0) * 32);
#pragma unroll
        for (int jp = 0; jp < 16; jp++) { float2 v = __ldg(wp + jp); wreg0[jp] = pk2(v.x, v.y); }
        b20 = __ldg(bf2 + lane * C + cg0);
        if (two_ch) {
            const float2* wq = reinterpret_cast<const float2*>(Wf2 + (lane * C + cg0 + 1) * 32);
#pragma unroll
            for (int jp = 0; jp < 16; jp++) { float2 v = __ldg(wq + jp); wreg1[jp] = pk2(v.x, v.y); }
            b21 = __ldg(bf2 + lane * C + cg0 + 1);
        } else {
#pragma unroll
            for (int jp = 0; jp < 16; jp++) wreg1[jp] = 0ull;
            b21 = 0.f;
        }
    }
    // Wf1 j-slice [8*cw, 8*cw+8) packed: 4 ull
    ull rw1s[4];
    {
        const float2* p1 = reinterpret_cast<const float2*>(Wf1 + lane * 32 + 8 * cw);
#pragma unroll
        for (int p = 0; p < 4; p++) { float2 v = __ldg(p1 + p); rw1s[p] = pk2(v.x, v.y); }
    }
    const float rbf1 = __ldg(bf1 + lane);

    // ---- ownership: slots {2cw, 2cw+1} (cw<3) or {6} ----
    const int nb  = two_ch ? 2 : 1;
    const int bs0 = two_ch ? 2 * cw : 6;

    // z0 for own batches -> sZ
    float z[2], ksum[2];
#pragma unroll
    for (int k = 0; k < 2; k++) {
        ksum[k] = 0.f;
        if (k < nb) {
            int gb = min(gbase + bs0 + k, 4095);
            float acc = __ldg(binit + lane);
            const float* xp = X + (size_t)gb * (L * C);
#pragma unroll
            for (int c = 0; c < C; c++) acc = fmaf(__ldg(xp + c), __ldg(Winit + lane * C + c), acc);
            z[k] = acc;
            sZ[bs0 + k][lane] = acc;
        }
    }

    // spline mapping: warp covers slots {2cw, 2cw+(lane>>4)}; 16 lanes/slot, 8 active
    const int sl = 2 * cw + (lane >> 4);
    const int dc = lane & 7;
    const bool dcact = ((lane >> 3) & 1) == 0;
    const int gsb = min(gbase + sl, 4095);
    const float* xrow = X + (size_t)gsb * (L * C) + ((dc < C) ? dc : 0);

    // initial dX(t=0) -> slot 0
    if (dcact) {
        float v = 0.f;
        if (dc < C) v = __ldg(xrow + C) - __ldg(xrow);
        sDX[0][sl][dc] = v;
    }
    __syncthreads();

    float t0 = 0.f;
#pragma unroll 1
    for (int i = 0; i < NSTEPS; i++, t0 += 0.5f) {
        // spline: t0+0.25 -> slot 2 ; t0+0.5 -> slot (i+1)&1
        if (dcact) {
            float vb = 0.f, vc = 0.f;
            if (dc < C) {
                vb = spline_eval(xrow, t0 + 0.25f);
                vc = spline_eval(xrow, t0 + 0.5f);
            }
            sDX[2][sl][dc] = vb;
            sDX[(i + 1) & 1][sl][dc] = vc;
        }
        const int slotA = i & 1, slotC = (i + 1) & 1;

#pragma unroll 1
        for (int s = 0; s < 4; s++) {
            const int slot = (s == 0) ? slotA : ((s == 3) ? slotC : 2);
            __syncthreads();   // A: zs (and sDX at s==0) visible

            // mm1 j-slice partials for all 7 batches
#pragma unroll
            for (int bs = 0; bs < NG; bs++) {
                const ulonglong2* zp = reinterpret_cast<const ulonglong2*>(&sZ[bs][8 * cw]);
                ulonglong2 q0 = zp[0], q1 = zp[1];
                ull p = 0ull;
                p = ffma2(q0.x, rw1s[0], p);
                p = ffma2(q0.y, rw1s[1], p);
                p = ffma2(q1.x, rw1s[2], p);
                p = ffma2(q1.y, rw1s[3], p);
                float u, v; upk2(p, u, v);
                sM1[cw][bs][lane] = u + v;
            }
            __syncthreads();   // B: mm1 partials visible

            // h1 combine + softplus (own batches)
#pragma unroll
            for (int k = 0; k < 2; k++) {
                if (k < nb) {
                    int bs = bs0 + k;
                    float p = sM1[0][bs][lane] + sM1[1][bs][lane]
                            + sM1[2][bs][lane] + sM1[3][bs][lane] + rbf1;
                    sH1[bs][lane] = sp_(p);
                }
            }
            __syncthreads();   // C: h1 visible

            // mm2 + tanh + einsum partial (own channels, all 7 batches)
            if (two_ch) {
#pragma unroll 1
                for (int bs = 0; bs < NG; bs++) {
                    const ulonglong2* hp = reinterpret_cast<const ulonglong2*>(&sH1[bs][0]);
                    ull acc0 = 0ull, acc1 = 0ull;
#pragma unroll
                    for (int q = 0; q < 8; q++) {
                        ulonglong2 hq = hp[q];
                        acc0 = ffma2(hq.x, wreg0[2 * q], acc0);
                        acc0 = ffma2(hq.y, wreg0[2 * q + 1], acc0);
                        acc1 = ffma2(hq.x, wreg1[2 * q], acc1);
                        acc1 = ffma2(hq.y, wreg1[2 * q + 1], acc1);
                    }
                    float u, v;
                    upk2(acc0, u, v); float g0 = tanh_(u + v + b20);
                    upk2(acc1, u, v); float g1 = tanh_(u + v + b21);
                    ull dxp = *reinterpret_cast<const ull*>(&sDX[slot][bs][cg0]);
                    ull e = ffma2(pk2(g0, g1), dxp, 0ull);
                    float e0, e1; upk2(e, e0, e1);
                    sPart[cw][bs][lane] = e0 + e1;
                }
            } else {
#pragma unroll 1
                for (int bs = 0; bs < NG; bs++) {
                    const ulonglong2* hp = reinterpret_cast<const ulonglong2*>(&sH1[bs][0]);
                    ull acc0 = 0ull;
#pragma unroll
                    for (int q = 0; q < 8; q++) {
                        ulonglong2 hq = hp[q];
                        acc0 = ffma2(hq.x, wreg0[2 * q], acc0);
                        acc0 = ffma2(hq.y, wreg0[2 * q + 1], acc0);
                    }
                    float u, v; upk2(acc0, u, v);
                    float g0 = tanh_(u + v + b20);
                    sPart[cw][bs][lane] = g0 * sDX[slot][bs][6];
                }
            }
            __syncthreads();   // D: einsum partials visible

            // combine + RK4 (own batches); write next zs
            const float wk = (s == 1 || s == 2) ? 2.f : 1.f;
            const float an = (s < 2) ? 0.25f : 0.5f;
#pragma unroll
            for (int k = 0; k < 2; k++) {
                if (k < nb) {
                    int bs = bs0 + k;
                    float kk = sPart[0][bs][lane] + sPart[1][bs][lane]
                             + sPart[2][bs][lane] + sPart[3][bs][lane];
                    ksum[k] = fmaf(wk, kk, ksum[k]);
                    float zsv;
                    if (s < 3) {
                        zsv = fmaf(an, kk, z[k]);
                    } else {
                        z[k] = fmaf(ksum[k], (1.f / 12.f), z[k]);  // h/6
                        ksum[k] = 0.f;
                        zsv = z[k];
                    }
                    sZ[bs][lane] = zsv;
                }
            }
        }
    }

    // ---- output head (own batches); sZ already holds final z (written at s==3) ----
    __syncwarp();
    float* so = &sM1[w][0][0];   // own-warp scratch [8][32]
    if (lane < 16) {
#pragma unroll
        for (int k = 0; k < 2; k++) {
            if (k < nb) {
                int bs = bs0 + k;
                float acc = __ldg(bo1 + lane);
#pragma unroll
                for (int hh = 0; hh < 32; hh++)
                    acc = fmaf(sZ[bs][hh], __ldg(Wo1 + lane * 32 + hh), acc);
                so[k * 32 + lane] = sp_(acc);
            }
        }
    }
    __syncwarp();
    if (lane < 3 * nb) {
        int k = lane / 3;
        int jo = lane - 3 * k;
        int gb = gbase + bs0 + k;
        if (gb < 4096) {
            float acc = __ldg(bo2 + jo);
#pragma unroll
            for (int i2 = 0; i2 < 16; i2++)
                acc = fmaf(so[k * 32 + i2], __ldg(Wo2 + jo * 16 + i2), acc);
            out[(size_t)gb * 3 + jo] = acc;
        }
    }
}

extern "C" void kernel_launch(void* const* d_in, const int* in_sizes, int n_in,
                              void* d_out, int out_size) {
    const float* X     = (const float*)d_in[0];
    const float* Winit = (const float*)d_in[1];
    const float* binit = (const float*)d_in[2];
    const float* Wf1   = (const float*)d_in[3];
    const float* bf1   = (const float*)d_in[4];
    const float* Wf2   = (const float*)d_in[5];
    const float* bf2   = (const float*)d_in[6];
    const float* Wo1   = (const float*)d_in[7];
    const float* bo1   = (const float*)d_in[8];
    const float* Wo2   = (const float*)d_in[9];
    const float* bo2   = (const float*)d_in[10];
    float* out = (float*)d_out;

    // 586 CTAs x 128 thr: 1 group x 7 batches = 4102 slots >= 4096 (tail guarded)
    cde_kernel<<<NCTA, 128>>>(X, Winit, binit, Wf1, bf1, Wf2, bf2,
                              Wo1, bo1, Wo2, bo2, out);
}

// round 8
// speedup vs baseline: 1.0491x; 1.0491x over previous
#include <cuda_runtime.h>

#define L 64
#define C 7
#define NSTEPS 126   // (L-1)*K, K=2, h=0.5
#define NG 7         // batches per group (CTA)
#define NCTA 586     // ceil(4096/7)

typedef unsigned long long ull;

__device__ __forceinline__ ull ffma2(ull a, ull b, ull c) {
    ull d;
    asm("fma.rn.f32x2 %0, %1, %2, %3;" : "=l"(d) : "l"(a), "l"(b), "l"(c));
    return d;
}
__device__ __forceinline__ ull pk2(float x, float y) {
    ull r;
    asm("mov.b64 %0, {%1, %2};" : "=l"(r) : "f"(x), "f"(y));
    return r;
}
__device__ __forceinline__ void upk2(ull v, float &x, float &y) {
    asm("mov.b64 {%0, %1}, %2;" : "=f"(x), "=f"(y) : "l"(v));
}
__device__ __forceinline__ float sp_(float x) {
    return fmaxf(x, 0.f) + __logf(1.f + __expf(-fabsf(x)));
}
__device__ __forceinline__ float tanh_(float x) {
    float y;
    asm("tanh.approx.f32 %0, %1;" : "=f"(y) : "f"(x));
    return y;
}

// cubic Hermite derivative: dX = m0 + (diff-m0)*f*(4-3f)
__device__ __forceinline__ float spline_eval(const float* __restrict__ xrow, float t) {
    int idx = (int)t;
    idx = min(idx, L - 2);
    float f = t - (float)idx;
    const float* p = xrow + idx * C;
    float x0 = __ldg(p);
    float x1 = __ldg(p + C);
    float diff = x1 - x0;
    float m0 = diff;
    if (idx > 0) m0 = x0 - __ldg(p - C);
    return fmaf((diff - m0) * f, fmaf(-3.f, f, 4.f), m0);
}

__global__ __launch_bounds__(128, 4)
void cde_kernel(const float* __restrict__ X,      // (4096,64,7)
                const float* __restrict__ Winit,  // (32,7)
                const float* __restrict__ binit,  // (32)
                const float* __restrict__ Wf1,    // (32,32)
                const float* __restrict__ bf1,    // (32)
                const float* __restrict__ Wf2,    // (224,32)
                const float* __restrict__ bf2,    // (224)
                const float* __restrict__ Wo1,    // (16,32)
                const float* __restrict__ bo1,    // (16)
                const float* __restrict__ Wo2,    // (3,16)
                const float* __restrict__ bo2,    // (3)
                float* __restrict__ out)          // (4096,3)
{
    // One CTA = 4 warps = one group serving 7 batches (slot 7 = dummy)
    __shared__ __align__(16) ull   sW1p[16][32];     // Wf1 j-pair packed: [jp][h] (4 KB)
    __shared__ __align__(16) float sZ[8][32];        // zs per batch slot
    __shared__ __align__(16) float sH1[8][32];       // h1
    __shared__ __align__(16) float sPart[4][8][32];  // einsum c-slice partials
    __shared__ __align__(16) float sDX[3][8][8];     // spline values

    const int tid  = threadIdx.x;
    const int w    = tid >> 5;
    const int lane = tid & 31;               // = h
    const int cw   = (w + blockIdx.x) & 3;   // rotated channel role (SMSP balance)
    const bool two_ch = (cw < 3);
    const int cg0  = two_ch ? 2 * cw : 6;
    const int gbase = blockIdx.x * NG;

    // mm1 batch ownership: w0..w2 -> 2 batches, w3 -> 1
    const int bs0 = 2 * w;
    const int nb  = (w < 3) ? 2 : 1;

    // Wf1 packed into smem: sW1p[jp][h] = (Wf1[h][2jp], Wf1[h][2jp+1])
    for (int idx = tid; idx < 512; idx += 128) {
        int jp = idx >> 5, h = idx & 31;
        sW1p[jp][h] = pk2(__ldg(Wf1 + h * 32 + 2 * jp), __ldg(Wf1 + h * 32 + 2 * jp + 1));
    }

    // ---- Wf2 owned channels (j-pair packed) in registers ----
    ull wreg0[16], wreg1[16];
    float b20, b21;
    {
        const float2* wp = reinterpret_cast<const float2*>(Wf2 + (lane * C + cg0) * 32);
#pragma unroll
        for (int jp = 0; jp < 16; jp++) { float2 v = __ldg(wp + jp); wreg0[jp] = pk2(v.x, v.y); }
        b20 = __ldg(bf2 + lane * C + cg0);
        if (two_ch) {
            const float2* wq = reinterpret_cast<const float2*>(Wf2 + (lane * C + cg0 + 1) * 32);
#pragma unroll
            for (int jp = 0; jp < 16; jp++) { float2 v = __ldg(wq + jp); wreg1[jp] = pk2(v.x, v.y); }
            b21 = __ldg(bf2 + lane * C + cg0 + 1);
        } else {
#pragma unroll
            for (int jp = 0; jp < 16; jp++) wreg1[jp] = 0ull;
            b21 = 0.f;
        }
    }
    const float rbf1 = __ldg(bf1 + lane);

    // z0 for own batches
    float z[2], zs[2], ksum[2];
#pragma unroll
    for (int k = 0; k < 2; k++) {
        ksum[k] = 0.f; z[k] = 0.f;
        if (k < nb) {
            int gb = min(gbase + bs0 + k, 4095);
            float acc = __ldg(binit + lane);
            const float* xp = X + (size_t)gb * (L * C);
#pragma unroll
            for (int c = 0; c < C; c++) acc = fmaf(__ldg(xp + c), __ldg(Winit + lane * C + c), acc);
            z[k] = acc;
        }
        zs[k] = z[k];
    }

    // spline: warp w covers slots {2w, 2w+(lane>>4)}; dc = lane&7; 8 active of 16
    const int sl = 2 * w + (lane >> 4);
    const int dc = lane & 7;
    const bool dcact = ((lane >> 3) & 1) == 0;
    const int gsb = min(gbase + sl, 4095);
    const float* xrow = X + (size_t)gsb * (L * C) + ((dc < C) ? dc : 0);

    // initial dX(t=0) -> slot 0
    if (dcact) {
        float v = 0.f;
        if (dc < C) v = __ldg(xrow + C) - __ldg(xrow);
        sDX[0][sl][dc] = v;
    }
    __syncthreads();   // sW1p + sDX slot0 visible

    float t0 = 0.f;
#pragma unroll 1
    for (int i = 0; i < NSTEPS; i++, t0 += 0.5f) {
        // spline: t0+0.25 -> slot 2 ; t0+0.5 -> slot (i+1)&1
        if (dcact) {
            float vb = 0.f, vc = 0.f;
            if (dc < C) {
                vb = spline_eval(xrow, t0 + 0.25f);
                vc = spline_eval(xrow, t0 + 0.5f);
            }
            sDX[2][sl][dc] = vb;
            sDX[(i + 1) & 1][sl][dc] = vc;
        }
        const int slotA = i & 1, slotC = (i + 1) & 1;

#pragma unroll 1
        for (int s = 0; s < 4; s++) {
            const int slot = (s == 0) ? slotA : ((s == 3) ? slotC : 2);

            // ---- mm1 (own batches, full j; Wf1 from smem, interleaved chains) ----
#pragma unroll
            for (int k = 0; k < 2; k++) if (k < nb) sZ[bs0 + k][lane] = zs[k];
            __syncwarp();
            ull a1_0 = 0ull, a1_1 = 0ull;
#pragma unroll
            for (int q = 0; q < 8; q++) {
                ull w0 = sW1p[2 * q][lane];
                ull w1 = sW1p[2 * q + 1][lane];
                ulonglong2 zq0 = *reinterpret_cast<const ulonglong2*>(&sZ[bs0][4 * q]);
                a1_0 = ffma2(zq0.x, w0, a1_0);
                a1_0 = ffma2(zq0.y, w1, a1_0);
                if (nb > 1) {
                    ulonglong2 zq1 = *reinterpret_cast<const ulonglong2*>(&sZ[bs0 + 1][4 * q]);
                    a1_1 = ffma2(zq1.x, w0, a1_1);
                    a1_1 = ffma2(zq1.y, w1, a1_1);
                }
            }
            {
                float u, v; upk2(a1_0, u, v);
                sH1[bs0][lane] = sp_(u + v + rbf1);
                if (nb > 1) {
                    upk2(a1_1, u, v);
                    sH1[bs0 + 1][lane] = sp_(u + v + rbf1);
                }
            }
            __syncthreads();   // h1 (and this step's sDX at s==0) visible

            // ---- mm2 + tanh + einsum partial (own channels, all 7 batches) ----
            if (two_ch) {
#pragma unroll 1
                for (int bs = 0; bs < NG; bs++) {
                    const ulonglong2* hp = reinterpret_cast<const ulonglong2*>(&sH1[bs][0]);
                    ull acc0 = 0ull, acc1 = 0ull;
#pragma unroll
                    for (int q = 0; q < 8; q++) {
                        ulonglong2 hq = hp[q];
                        acc0 = ffma2(hq.x, wreg0[2 * q], acc0);
                        acc0 = ffma2(hq.y, wreg0[2 * q + 1], acc0);
                        acc1 = ffma2(hq.x, wreg1[2 * q], acc1);
                        acc1 = ffma2(hq.y, wreg1[2 * q + 1], acc1);
                    }
                    float u, v;
                    upk2(acc0, u, v); float g0 = tanh_(u + v + b20);
                    upk2(acc1, u, v); float g1 = tanh_(u + v + b21);
                    ull dxp = *reinterpret_cast<const ull*>(&sDX[slot][bs][cg0]);
                    ull e = ffma2(pk2(g0, g1), dxp, 0ull);
                    float e0, e1; upk2(e, e0, e1);
                    sPart[cw][bs][lane] = e0 + e1;
                }
            } else {
#pragma unroll 1
                for (int bs = 0; bs < NG; bs++) {
                    const ulonglong2* hp = reinterpret_cast<const ulonglong2*>(&sH1[bs][0]);
                    ull acc0 = 0ull;
#pragma unroll
                    for (int q = 0; q < 8; q++) {
                        ulonglong2 hq = hp[q];
                        acc0 = ffma2(hq.x, wreg0[2 * q], acc0);
                        acc0 = ffma2(hq.y, wreg0[2 * q + 1], acc0);
                    }
                    float u, v; upk2(acc0, u, v);
                    float g0 = tanh_(u + v + b20);
                    sPart[cw][bs][lane] = g0 * sDX[slot][bs][6];
                }
            }
            __syncthreads();   // partials visible

            // ---- combine + RK4 (own batches) ----
            const float wk = (s == 1 || s == 2) ? 2.f : 1.f;
            const float an = (s < 2) ? 0.25f : 0.5f;
#pragma unroll
            for (int k = 0; k < 2; k++) {
                if (k < nb) {
                    int bs = bs0 + k;
                    float kk = sPart[0][bs][lane] + sPart[1][bs][lane]
                             + sPart[2][bs][lane] + sPart[3][bs][lane];
                    ksum[k] = fmaf(wk, kk, ksum[k]);
                    if (s < 3) {
                        zs[k] = fmaf(an, kk, z[k]);
                    } else {
                        z[k] = fmaf(ksum[k], (1.f / 12.f), z[k]);  // h/6
                        ksum[k] = 0.f;
                        zs[k] = z[k];
                    }
                }
            }
        }
    }

    __syncthreads();   // all combines done before sZ/sPart reuse below

    // ---- output head (own batches) ----
#pragma unroll
    for (int k = 0; k < 2; k++) if (k < nb) sZ[bs0 + k][lane] = z[k];
    __syncwarp();
    float* so = &sPart[w][0][0];   // own-warp scratch [2][32]
    if (lane < 16) {
#pragma unroll
        for (int k = 0; k < 2; k++) {
            if (k < nb) {
                float acc = __ldg(bo1 + lane);
#pragma unroll
                for (int hh = 0; hh < 32; hh++)
                    acc = fmaf(sZ[bs0 + k][hh], __ldg(Wo1 + lane * 32 + hh), acc);
                so[k * 32 + lane] = sp_(acc);
            }
        }
    }
    __syncwarp();
    if (lane < 3 * nb) {
        int k = lane / 3;
        int jo = lane - 3 * k;
        int gb = gbase + bs0 + k;
        if (gb < 4096) {
            float acc = __ldg(bo2 + jo);
#pragma unroll
            for (int i2 = 0; i2 < 16; i2++)
                acc = fmaf(so[k * 32 + i2], __ldg(Wo2 + jo * 16 + i2), acc);
            out[(size_t)gb * 3 + jo] = acc;
        }
    }
}

extern "C" void kernel_launch(void* const* d_in, const int* in_sizes, int n_in,
                              void* d_out, int out_size) {
    const float* X     = (const float*)d_in[0];
    const float* Winit = (const float*)d_in[1];
    const float* binit = (const float*)d_in[2];
    const float* Wf1   = (const float*)d_in[3];
    const float* bf1   = (const float*)d_in[4];
    const float* Wf2   = (const float*)d_in[5];
    const float* bf2   = (const float*)d_in[6];
    const float* Wo1   = (const float*)d_in[7];
    const float* bo1   = (const float*)d_in[8];
    const float* Wo2   = (const float*)d_in[9];
    const float* bo2   = (const float*)d_in[10];
    float* out = (float*)d_out;

    // 586 CTAs x 128 thr, 7 batches each = 4102 slots >= 4096 (tail guarded)
    cde_kernel<<<NCTA, 128>>>(X, Winit, binit, Wf1, bf1, Wf2, bf2,
                              Wo1, bo1, Wo2, bo2, out);
}

// round 9
// speedup vs baseline: 1.1484x; 1.0947x over previous
#include <cuda_runtime.h>

#define L 64
#define C 7
#define NSTEPS 126   // (L-1)*K, K=2, h=0.5
#define NBPAIR 7     // batches per warp-pair
#define NCTA 293     // 2 pairs per CTA

typedef unsigned long long ull;

__device__ __forceinline__ ull ffma2(ull a, ull b, ull c) {
    ull d;
    asm("fma.rn.f32x2 %0, %1, %2, %3;" : "=l"(d) : "l"(a), "l"(b), "l"(c));
    return d;
}
__device__ __forceinline__ ull pk2(float x, float y) {
    ull r;
    asm("mov.b64 %0, {%1, %2};" : "=l"(r) : "f"(x), "f"(y));
    return r;
}
__device__ __forceinline__ void upk2(ull v, float &x, float &y) {
    asm("mov.b64 {%0, %1}, %2;" : "=f"(x), "=f"(y) : "l"(v));
}
__device__ __forceinline__ float sp_(float x) {
    return fmaxf(x, 0.f) + __logf(1.f + __expf(-fabsf(x)));
}
__device__ __forceinline__ float tanh_(float x) {
    float y;
    asm("tanh.approx.f32 %0, %1;" : "=f"(y) : "f"(x));
    return y;
}

// cubic Hermite derivative: dX = m0 + (diff-m0)*f*(4-3f)
__device__ __forceinline__ float spline_eval(const float* __restrict__ xrow, float t) {
    int idx = (int)t;
    idx = min(idx, L - 2);
    float f = t - (float)idx;
    const float* p = xrow + idx * C;
    float x0 = __ldg(p);
    float x1 = __ldg(p + C);
    float diff = x1 - x0;
    float m0 = diff;
    if (idx > 0) m0 = x0 - __ldg(p - C);
    return fmaf((diff - m0) * f, fmaf(-3.f, f, 4.f), m0);
}

__global__ __launch_bounds__(128, 2)
void cde_kernel(const float* __restrict__ X,      // (4096,64,7)
                const float* __restrict__ Winit,  // (32,7)
                const float* __restrict__ binit,  // (32)
                const float* __restrict__ Wf1,    // (32,32)
                const float* __restrict__ bf1,    // (32)
                const float* __restrict__ Wf2,    // (224,32)
                const float* __restrict__ bf2,    // (224)
                const float* __restrict__ Wo1,    // (16,32)
                const float* __restrict__ bo1,    // (16)
                const float* __restrict__ Wo2,    // (3,16)
                const float* __restrict__ bo2,    // (3)
                float* __restrict__ out)          // (4096,3)
{
    // 4 warps = 2 pairs; pair serves 7 batches (+1 dummy slot); A: c0-3, B: c4-7(pad)
    __shared__ __align__(16) float sZ[2][8][32];
    __shared__ __align__(16) float sH1[2][8][32];
    __shared__ __align__(16) float sDX[2][3][8][8];
    __shared__ __align__(16) float sPart[4][8][32];

    const int tid  = threadIdx.x;
    const int w    = tid >> 5;
    const int lane = tid & 31;          // = h
    const int pair = w >> 1;
    const int isB  = w & 1;
    const int partner = w ^ 1;
    const int gpair = blockIdx.x * 2 + pair;
    const int pairbase = gpair * NBPAIR;
    const int ownbase  = pairbase + isB * 4;     // A owns 4 (bs 0-3), B owns 3 (bs 4-6)
    const int nk = isB ? 3 : 4;

    // ---- Wf2 own c-half, j-pair packed, in registers ----
    ull wreg[4][16];
    float b2[4];
#pragma unroll
    for (int cp = 0; cp < 4; cp++) {
        int cg = isB * 4 + cp;
        if (cg < C) {
            const float2* wp = reinterpret_cast<const float2*>(Wf2 + (lane * C + cg) * 32);
#pragma unroll
            for (int jp = 0; jp < 16; jp++) { float2 v = __ldg(wp + jp); wreg[cp][jp] = pk2(v.x, v.y); }
            b2[cp] = __ldg(bf2 + lane * C + cg);
        } else {
#pragma unroll
            for (int jp = 0; jp < 16; jp++) wreg[cp][jp] = 0ull;
            b2[cp] = 0.f;
        }
    }
    ull rw1[16];
    {
        const float2* p1 = reinterpret_cast<const float2*>(Wf1 + lane * 32);
#pragma unroll
        for (int jp = 0; jp < 16; jp++) { float2 v = __ldg(p1 + jp); rw1[jp] = pk2(v.x, v.y); }
    }
    const float rbf1 = __ldg(bf1 + lane);

    // dX mapping: lane -> (db 0..3, dc 0..7); B's db=3 -> dummy slot 7
    const int db = lane >> 3;
    const int dc = lane & 7;
    const int sbatch = min(ownbase + db, 4095);
    const float* xrow = X + (size_t)sbatch * (L * C) + ((dc < C) ? dc : 0);

    // z0 for own (clamped) batches
    float z[4];
#pragma unroll
    for (int k = 0; k < 4; k++) {
        int gb = min(ownbase + k, 4095);
        float acc = __ldg(binit + lane);
        const float* xp = X + (size_t)gb * (L * C);
#pragma unroll
        for (int c = 0; c < C; c++) acc = fmaf(__ldg(xp + c), __ldg(Winit + lane * C + c), acc);
        z[k] = acc;
    }

    // initial dX(t=0) -> slot 0
    {
        float v = 0.f;
        if (dc < C) v = __ldg(xrow + C) - __ldg(xrow);
        sDX[pair][0][isB * 4 + db][dc] = v;
    }

    float t0 = 0.f;
#pragma unroll 1
    for (int i = 0; i < NSTEPS; i++, t0 += 0.5f) {
        // spline: t0+0.25 -> slot 2 ; t0+0.5 -> slot (i+1)&1
        {
            float vb = 0.f, vc = 0.f;
            if (dc < C) {
                vb = spline_eval(xrow, t0 + 0.25f);
                vc = spline_eval(xrow, t0 + 0.5f);
            }
            sDX[pair][2][isB * 4 + db][dc] = vb;
            sDX[pair][(i + 1) & 1][isB * 4 + db][dc] = vc;
        }
        const int slotA = i & 1, slotC = (i + 1) & 1;

        float zs[4], ksum[4];
#pragma unroll
        for (int k = 0; k < 4; k++) { zs[k] = z[k]; ksum[k] = 0.f; }

#pragma unroll 1
        for (int s = 0; s < 4; s++) {
            const int slot = (s == 0) ? slotA : ((s == 3) ? slotC : 2);

            // own zs -> sZ (B's k=3 goes to dummy slot 7)
            __syncwarp();
#pragma unroll
            for (int k = 0; k < 4; k++) sZ[pair][isB * 4 + k][lane] = zs[k];
            __syncwarp();

            // mm1: 4 interleaved accumulator chains
            ull a1[4];
#pragma unroll
            for (int k = 0; k < 4; k++) a1[k] = 0ull;
#pragma unroll
            for (int q = 0; q < 8; q++) {
#pragma unroll
                for (int k = 0; k < 4; k++) {
                    ulonglong2 zq = *reinterpret_cast<const ulonglong2*>(&sZ[pair][isB * 4 + k][4 * q]);
                    a1[k] = ffma2(zq.x, rw1[2 * q], a1[k]);
                    a1[k] = ffma2(zq.y, rw1[2 * q + 1], a1[k]);
                }
            }
            float pre[4];
#pragma unroll
            for (int k = 0; k < 4; k++) { float u, v; upk2(a1[k], u, v); pre[k] = u + v + rbf1; }
#pragma unroll
            for (int k = 0; k < 4; k++) sH1[pair][isB * 4 + k][lane] = sp_(pre[k]);
            asm volatile("bar.sync %0, 64;" :: "r"(pair + 1) : "memory");

            // ---- mm2: batches processed in PAIRS (cross-batch tail overlap) ----
#pragma unroll 1
            for (int bp = 0; bp < 3; bp++) {
                const int bs = 2 * bp;
                const ulonglong2 dxq0 = *reinterpret_cast<const ulonglong2*>(&sDX[pair][slot][bs][isB * 4]);
                const ulonglong2 dxq1 = *reinterpret_cast<const ulonglong2*>(&sDX[pair][slot][bs + 1][isB * 4]);
                const ulonglong2* hp0 = reinterpret_cast<const ulonglong2*>(&sH1[pair][bs][0]);
                const ulonglong2* hp1 = reinterpret_cast<const ulonglong2*>(&sH1[pair][bs + 1][0]);
                ull a00 = 0ull, a01 = 0ull, a02 = 0ull, a03 = 0ull;
                ull a10 = 0ull, a11 = 0ull, a12 = 0ull, a13 = 0ull;
#pragma unroll
                for (int q = 0; q < 8; q++) {
                    ulonglong2 h0 = hp0[q];
                    ulonglong2 h1 = hp1[q];
                    a00 = ffma2(h0.x, wreg[0][2 * q], a00);
                    a01 = ffma2(h0.x, wreg[1][2 * q], a01);
                    a02 = ffma2(h0.x, wreg[2][2 * q], a02);
                    a03 = ffma2(h0.x, wreg[3][2 * q], a03);
                    a10 = ffma2(h1.x, wreg[0][2 * q], a10);
                    a11 = ffma2(h1.x, wreg[1][2 * q], a11);
                    a12 = ffma2(h1.x, wreg[2][2 * q], a12);
                    a13 = ffma2(h1.x, wreg[3][2 * q], a13);
                    a00 = ffma2(h0.y, wreg[0][2 * q + 1], a00);
                    a01 = ffma2(h0.y, wreg[1][2 * q + 1], a01);
                    a02 = ffma2(h0.y, wreg[2][2 * q + 1], a02);
                    a03 = ffma2(h0.y, wreg[3][2 * q + 1], a03);
                    a10 = ffma2(h1.y, wreg[0][2 * q + 1], a10);
                    a11 = ffma2(h1.y, wreg[1][2 * q + 1], a11);
                    a12 = ffma2(h1.y, wreg[2][2 * q + 1], a12);
                    a13 = ffma2(h1.y, wreg[3][2 * q + 1], a13);
                }
                float u, v;
                float g00, g01, g02, g03, g10, g11, g12, g13;
                upk2(a00, u, v); g00 = tanh_(u + v + b2[0]);
                upk2(a10, u, v); g10 = tanh_(u + v + b2[0]);
                upk2(a01, u, v); g01 = tanh_(u + v + b2[1]);
                upk2(a11, u, v); g11 = tanh_(u + v + b2[1]);
                upk2(a02, u, v); g02 = tanh_(u + v + b2[2]);
                upk2(a12, u, v); g12 = tanh_(u + v + b2[2]);
                upk2(a03, u, v); g03 = tanh_(u + v + b2[3]);
                upk2(a13, u, v); g13 = tanh_(u + v + b2[3]);
                ull e0 = ffma2(pk2(g00, g01), dxq0.x, ffma2(pk2(g02, g03), dxq0.y, 0ull));
                ull e1 = ffma2(pk2(g10, g11), dxq1.x, ffma2(pk2(g12, g13), dxq1.y, 0ull));
                float e0a, e0b, e1a, e1b;
                upk2(e0, e0a, e0b);
                upk2(e1, e1a, e1b);
                sPart[w][bs][lane]     = e0a + e0b;
                sPart[w][bs + 1][lane] = e1a + e1b;
            }
            {   // bs = 6 singleton
                const int bs = 6;
                const ulonglong2 dxq0 = *reinterpret_cast<const ulonglong2*>(&sDX[pair][slot][bs][isB * 4]);
                const ulonglong2* hp0 = reinterpret_cast<const ulonglong2*>(&sH1[pair][bs][0]);
                ull a00 = 0ull, a01 = 0ull, a02 = 0ull, a03 = 0ull;
#pragma unroll
                for (int q = 0; q < 8; q++) {
                    ulonglong2 h0 = hp0[q];
                    a00 = ffma2(h0.x, wreg[0][2 * q], a00);
                    a01 = ffma2(h0.x, wreg[1][2 * q], a01);
                    a02 = ffma2(h0.x, wreg[2][2 * q], a02);
                    a03 = ffma2(h0.x, wreg[3][2 * q], a03);
                    a00 = ffma2(h0.y, wreg[0][2 * q + 1], a00);
                    a01 = ffma2(h0.y, wreg[1][2 * q + 1], a01);
                    a02 = ffma2(h0.y, wreg[2][2 * q + 1], a02);
                    a03 = ffma2(h0.y, wreg[3][2 * q + 1], a03);
                }
                float u, v, g0, g1, g2, g3;
                upk2(a00, u, v); g0 = tanh_(u + v + b2[0]);
                upk2(a01, u, v); g1 = tanh_(u + v + b2[1]);
                upk2(a02, u, v); g2 = tanh_(u + v + b2[2]);
                upk2(a03, u, v); g3 = tanh_(u + v + b2[3]);
                ull e = ffma2(pk2(g0, g1), dxq0.x, ffma2(pk2(g2, g3), dxq0.y, 0ull));
                float ea, eb; upk2(e, ea, eb);
                sPart[w][bs][lane] = ea + eb;
            }
            asm volatile("bar.sync %0, 64;" :: "r"(pair + 1) : "memory");

            // combine partials for own real batches; RK4 bookkeeping
            const float wk = (s == 1 || s == 2) ? 2.f : 1.f;
            const float an = (s < 2) ? 0.25f : 0.5f;
#pragma unroll
            for (int k = 0; k < 4; k++) {
                if (k < nk) {
                    int bs = isB * 4 + k;
                    float kk = sPart[w][bs][lane] + sPart[partner][bs][lane];
                    ksum[k] = fmaf(wk, kk, ksum[k]);
                    zs[k]   = fmaf(an, kk, z[k]);
                }
            }
        }
#pragma unroll
        for (int k = 0; k < 4; k++) z[k] = fmaf(ksum[k], (1.f / 12.f), z[k]);  // h/6
    }

    // partner must finish reading sPart/sH1 before scratch reuse
    asm volatile("bar.sync %0, 64;" :: "r"(pair + 1) : "memory");

    // output head (own real batches)
#pragma unroll
    for (int k = 0; k < 4; k++) sZ[pair][isB * 4 + k][lane] = z[k];
    __syncwarp();
    float* so = &sPart[w][0][0];   // [4][32] scratch, own-warp only
    if (lane < 16) {
#pragma unroll
        for (int k = 0; k < 4; k++) {
            float acc = __ldg(bo1 + lane);
#pragma unroll
            for (int hh = 0; hh < 32; hh++)
                acc = fmaf(sZ[pair][isB * 4 + k][hh], __ldg(Wo1 + lane * 32 + hh), acc);
            so[k * 32 + lane] = sp_(acc);
        }
    }
    __syncwarp();
    if (lane < 12) {
        int k = lane / 3;
        int jo = lane - 3 * k;
        int gb = ownbase + k;
        if (k < nk && gb < 4096) {
            float acc = __ldg(bo2 + jo);
#pragma unroll
            for (int i2 = 0; i2 < 16; i2++)
                acc = fmaf(so[k * 32 + i2], __ldg(Wo2 + jo * 16 + i2), acc);
            out[(size_t)gb * 3 + jo] = acc;
        }
    }
}

extern "C" void kernel_launch(void* const* d_in, const int* in_sizes, int n_in,
                              void* d_out, int out_size) {
    const float* X     = (const float*)d_in[0];
    const float* Winit = (const float*)d_in[1];
    const float* binit = (const float*)d_in[2];
    const float* Wf1   = (const float*)d_in[3];
    const float* bf1   = (const float*)d_in[4];
    const float* Wf2   = (const float*)d_in[5];
    const float* bf2   = (const float*)d_in[6];
    const float* Wo1   = (const float*)d_in[7];
    const float* bo1   = (const float*)d_in[8];
    const float* Wo2   = (const float*)d_in[9];
    const float* bo2   = (const float*)d_in[10];
    float* out = (float*)d_out;

    // 293 CTAs x 128 thr: 2 pairs/CTA x 7 batches = 4102 slots >= 4096 (tail guarded)
    cde_kernel<<<NCTA, 128>>>(X, Winit, binit, Wf1, bf1, Wf2, bf2,
                              Wo1, bo1, Wo2, bo2, out);
}